// round 3
// baseline (speedup 1.0000x reference)
#include <cuda_runtime.h>
#include <cuda_bf16.h>
#include <math_constants.h>
#include <cstdint>

#define N_BOXES   262144
#define STRIDE    85
#define N_CLASSES 80
#define CONF_THRES 0.8f
#define NMS_THRES  0.4f
#define MAX_DET    300
#define NSHARD    4
#define SHARDCAP  256
#define CAP       (NSHARD * SHARDCAP)   // 1024 per class
#define MAXKEEP   2048
#define FULLMASK  0xffffffffu
#define CLS_WARPS 57344                  // classify-kernel warp budget (>= ~52429 valid)

// ---------------- device scratch ----------------
__device__ int   g_cnt4[N_CLASSES * NSHARD];
__device__ float g_x1[N_CLASSES * CAP];
__device__ float g_y1[N_CLASSES * CAP];
__device__ float g_x2[N_CLASSES * CAP];
__device__ float g_y2[N_CLASSES * CAP];
__device__ float g_sc[N_CLASSES * CAP];
__device__ float g_cf[N_CLASSES * CAP];

__device__ int   g_nvalid;
__device__ int   g_vidx[N_BOXES];

__device__ int   g_keep_n;
__device__ float g_keep_score[MAXKEEP];
__device__ float g_keep_conf [MAXKEEP];
__device__ int   g_keep_cls  [MAXKEEP];

__device__ __forceinline__ bool before(float ak, int ai, float bk, int bi) {
    return (ak > bk) || (ak == bk && ai < bi);
}

// ---------------- kernel 0: reset (grid covers g_sc) ----------------
__global__ void k_init() {
    int i = blockIdx.x * blockDim.x + threadIdx.x;
    if (i < N_CLASSES * CAP) g_sc[i] = -CUDART_INF_F;
    if (i < N_CLASSES * NSHARD) g_cnt4[i] = 0;
    if (i == 0) { g_keep_n = 0; g_nvalid = 0; }
}

// ---------------- kernel 1: probe obj + warp-aggregated compaction ----------------
__global__ void k_probe(const float* __restrict__ det) {
    int i = blockIdx.x * blockDim.x + threadIdx.x;
    int lane = threadIdx.x & 31;
    float obj = det[(size_t)i * STRIDE + 4];
    bool v = (obj >= CONF_THRES);
    unsigned mask = __ballot_sync(FULLMASK, v);
    int npop = __popc(mask);
    int base = 0;
    if (lane == 0 && npop) base = atomicAdd(&g_nvalid, npop);
    base = __shfl_sync(FULLMASK, base, 0);
    if (v) {
        int off = __popc(mask & ((1u << lane) - 1u));
        g_vidx[base + off] = i;
    }
}

// ---------------- kernel 2: warp-per-valid-box classify/bucket ----------------
__global__ void k_classify(const float* __restrict__ det) {
    int gw   = (blockIdx.x * blockDim.x + threadIdx.x) >> 5;
    int lane = threadIdx.x & 31;
    int nv = g_nvalid;
    if (gw >= nv) return;

    int vid = g_vidx[gw];
    const float* p = det + (size_t)vid * STRIDE;

    float a  = p[lane];
    float b2 = p[lane + 32];
    float c2 = (lane < 21) ? p[lane + 64] : -1e30f;

    float bv = -1e30f; int bi = 0;
    if (lane >= 5)            { bv = a;  bi = lane - 5;  }
    if (b2 > bv)              { bv = b2; bi = lane + 27; }
    if (lane < 21 && c2 > bv) { bv = c2; bi = lane + 59; }

    #pragma unroll
    for (int off = 16; off; off >>= 1) {
        float ov = __shfl_down_sync(FULLMASK, bv, off);
        int   oi = __shfl_down_sync(FULLMASK, bi, off);
        if (ov > bv || (ov == bv && oi < bi)) { bv = ov; bi = oi; }
    }

    float x = __shfl_sync(FULLMASK, a, 0);
    float y = __shfl_sync(FULLMASK, a, 1);
    float w = __shfl_sync(FULLMASK, a, 2);
    float h = __shfl_sync(FULLMASK, a, 3);
    float o = __shfl_sync(FULLMASK, a, 4);

    if (lane == 0) {
        float conf  = bv;
        float score = __fmul_rn(o, conf);
        float hw = __fmul_rn(w, 0.5f);
        float hh = __fmul_rn(h, 0.5f);
        int shard = blockIdx.x & (NSHARD - 1);
        int local = atomicAdd(&g_cnt4[bi * NSHARD + shard], 1);
        if (local < SHARDCAP) {
            int idx = bi * CAP + shard * SHARDCAP + local;
            g_x1[idx] = __fsub_rn(x, hw);
            g_y1[idx] = __fsub_rn(y, hh);
            g_x2[idx] = __fadd_rn(x, hw);
            g_y2[idx] = __fadd_rn(y, hh);
            g_sc[idx] = score;
            g_cf[idx] = conf;
        }
    }
}

// ---------------- kernel 3: per-class NMS with rank-sort ----------------
__global__ __launch_bounds__(1024) void k_nms() {
    __shared__ float skin[CAP];                      // input keys by slot
    __shared__ float skey[CAP], sconf[CAP];          // sorted
    __shared__ float sx1[CAP], sy1[CAP], sx2[CAP], sy2[CAP];
    __shared__ int   scnt[NSHARD];
    __shared__ int   s_next;

    int c = blockIdx.x;
    int t = threadIdx.x;
    int base = c * CAP;

    if (t < NSHARD) {
        int v = g_cnt4[c * NSHARD + t];
        scnt[t] = (v > SHARDCAP) ? SHARDCAP : v;
    }
    __syncthreads();
    int n = scnt[0] + scnt[1] + scnt[2] + scnt[3];
    if (n == 0) return;

    int shard = t >> 8, local = t & (SHARDCAP - 1);
    bool real = (local < scnt[shard]);
    float key = real ? g_sc[base + t] : -CUDART_INF_F;
    skin[t] = key;
    __syncthreads();

    // rank by (key desc, slot asc), scanning only live prefix of each shard
    int r = 0;
    if (real) {
        #pragma unroll
        for (int s = 0; s < NSHARD; s++) {
            int cs = scnt[s];
            int o = s * SHARDCAP;
            for (int j = 0; j < cs; j++, o++) {
                float ok = skin[o];
                if ((ok > key) || (ok == key && o < t)) r++;
            }
        }
        // scatter into sorted position
        skey[r]  = key;
        sconf[r] = g_cf[base + t];
        sx1[r] = g_x1[base + t]; sy1[r] = g_y1[base + t];
        sx2[r] = g_x2[base + t]; sy2[r] = g_y2[base + t];
    }
    __syncthreads();

    // thread t owns sorted position t
    float bx1 = 0, by1 = 0, bx2 = 0, by2 = 0, a2 = 0;
    bool alive = (t < n);
    if (alive) {
        bx1 = sx1[t]; by1 = sy1[t]; bx2 = sx2[t]; by2 = sy2[t];
        a2 = __fmul_rn(__fadd_rn(__fsub_rn(bx2, bx1), 1.0f),
                       __fadd_rn(__fsub_rn(by2, by1), 1.0f));
    }
    int lane = t & 31;

    int cur = 0;
    while (cur < n) {
        if (t == 0) {
            s_next = n;
            int kk = atomicAdd(&g_keep_n, 1);
            if (kk < MAXKEEP) {
                g_keep_score[kk] = skey[cur];
                g_keep_conf [kk] = sconf[cur];
                g_keep_cls  [kk] = c;
            }
        }
        __syncthreads();

        float px1 = sx1[cur], py1 = sy1[cur], px2 = sx2[cur], py2 = sy2[cur];
        float pa  = __fmul_rn(__fadd_rn(__fsub_rn(px2, px1), 1.0f),
                              __fadd_rn(__fsub_rn(py2, py1), 1.0f));

        int cand = n;
        if (alive && t > cur) {
            float xx1 = fmaxf(px1, bx1), yy1 = fmaxf(py1, by1);
            float xx2 = fminf(px2, bx2), yy2 = fminf(py2, by2);
            float iw  = fmaxf(__fadd_rn(__fsub_rn(xx2, xx1), 1.0f), 0.0f);
            float ih  = fmaxf(__fadd_rn(__fsub_rn(yy2, yy1), 1.0f), 0.0f);
            float inter = __fmul_rn(iw, ih);
            float den = __fadd_rn(__fsub_rn(__fadd_rn(pa, a2), inter), 1e-16f);
            float iou = __fdiv_rn(inter, den);
            if (iou > NMS_THRES) alive = false;
            else                 cand = t;
        }
        #pragma unroll
        for (int off = 16; off; off >>= 1)
            cand = min(cand, __shfl_xor_sync(FULLMASK, cand, off));
        if (lane == 0 && cand < n) atomicMin(&s_next, cand);
        __syncthreads();
        cur = s_next;
        __syncthreads();
    }
}

// ---------------- kernel 4: rank-select top-300 + conf re-rank, emit ----------------
__global__ __launch_bounds__(1024) void k_final(float* __restrict__ out, int out_size) {
    __shared__ float sk[MAXKEEP];
    __shared__ float s_conf[MAX_DET];
    __shared__ int   s_cls [MAX_DET];
    __shared__ float s_outc[MAX_DET];
    __shared__ float s_outp[MAX_DET];

    int t = threadIdx.x;
    int K = g_keep_n; if (K > MAXKEEP) K = MAXKEEP;
    int Kc = (K < MAX_DET) ? K : MAX_DET;

    float k0 = (t        < K) ? g_keep_score[t]        : -CUDART_INF_F;
    float k1 = (t + 1024 < K) ? g_keep_score[t + 1024] : -CUDART_INF_F;
    sk[t] = k0; sk[t + 1024] = k1;
    if (t < MAX_DET) { s_outc[t] = 0.0f; s_outp[t] = 0.0f; }
    __syncthreads();

    // global score rank (key desc, keep-idx asc)
    int r0 = 0, r1 = 0;
    for (int i = 0; i < K; i++) {
        float ok = sk[i];
        if ((ok > k0) || (ok == k0 && i < t))        r0++;
        if ((ok > k1) || (ok == k1 && i < t + 1024)) r1++;
    }
    if (t < K && r0 < Kc)        { s_conf[r0] = g_keep_conf[t];        s_cls[r0] = g_keep_cls[t]; }
    if (t + 1024 < K && r1 < Kc) { s_conf[r1] = g_keep_conf[t + 1024]; s_cls[r1] = g_keep_cls[t + 1024]; }
    __syncthreads();

    // conf rank among selected (conf desc, ties -> larger score-rank first)
    if (t < Kc) {
        float mc = s_conf[t];
        int pos = 0;
        for (int j = 0; j < Kc; j++) {
            float oc = s_conf[j];
            if ((oc > mc) || (oc == mc && j > t)) pos++;
        }
        s_outc[pos] = (float)s_cls[t];
        s_outp[pos] = mc;
    }
    __syncthreads();

    if (t < MAX_DET) {
        if (t < out_size)            out[t]           = s_outc[t];
        if (MAX_DET + t < out_size)  out[MAX_DET + t] = s_outp[t];
    }
}

// ---------------- launch ----------------
extern "C" void kernel_launch(void* const* d_in, const int* in_sizes, int n_in,
                              void* d_out, int out_size) {
    const float* det = (const float*)d_in[0];
    float* out = (float*)d_out;

    k_init<<<(N_CLASSES * CAP + 255) / 256, 256>>>();
    k_probe<<<N_BOXES / 256, 256>>>(det);
    k_classify<<<CLS_WARPS / 8, 256>>>(det);
    k_nms<<<N_CLASSES, 1024>>>();
    k_final<<<1, 1024>>>(out, out_size);
}

// round 4
// speedup vs baseline: 1.6869x; 1.6869x over previous
#include <cuda_runtime.h>
#include <cuda_bf16.h>
#include <math_constants.h>
#include <cstdint>

#define N_BOXES   262144
#define STRIDE    85
#define N_CLASSES 80
#define CONF_THRES 0.8f
#define NMS_THRES  0.4f
#define MAX_DET    300
#define NSHARD    4
#define SHARDCAP  256
#define CAP       (NSHARD * SHARDCAP)   // 1024 slots per class
#define MAXKEEP   2048
#define FULLMASK  0xffffffffu
#define CLS_WARPS 57344                  // >= ~52429 expected valid (+24 sigma)

// ---------------- device scratch ----------------
__device__ int   g_cnt4[N_CLASSES * NSHARD];
__device__ float g_x1[N_CLASSES * CAP];
__device__ float g_y1[N_CLASSES * CAP];
__device__ float g_x2[N_CLASSES * CAP];
__device__ float g_y2[N_CLASSES * CAP];
__device__ float g_sc[N_CLASSES * CAP];
__device__ float g_cf[N_CLASSES * CAP];

__device__ int   g_nvalid;
__device__ int   g_vidx[N_BOXES];

__device__ int   g_keep_n;
__device__ float g_keep_score[MAXKEEP];
__device__ float g_keep_conf [MAXKEEP];
__device__ int   g_keep_cls  [MAXKEEP];

__device__ __forceinline__ bool before(float ak, int ai, float bk, int bi) {
    return (ak > bk) || (ak == bk && ai < bi);
}

// ---------------- kernel 0: reset ----------------
__global__ void k_init() {
    int i = blockIdx.x * blockDim.x + threadIdx.x;
    if (i < N_CLASSES * CAP) g_sc[i] = -CUDART_INF_F;   // empty slots sort to the back
    if (i < N_CLASSES * NSHARD) g_cnt4[i] = 0;
    if (i == 0) { g_keep_n = 0; g_nvalid = 0; }
}

// ---------------- kernel 1: obj probe + warp-aggregated compaction ----------------
__global__ void k_probe(const float* __restrict__ det) {
    int i = blockIdx.x * blockDim.x + threadIdx.x;
    int lane = threadIdx.x & 31;
    float obj = det[(size_t)i * STRIDE + 4];
    bool v = (obj >= CONF_THRES);
    unsigned mask = __ballot_sync(FULLMASK, v);
    int npop = __popc(mask);
    int base = 0;
    if (lane == 0 && npop) base = atomicAdd(&g_nvalid, npop);
    base = __shfl_sync(FULLMASK, base, 0);
    if (v) {
        int off = __popc(mask & ((1u << lane) - 1u));
        g_vidx[base + off] = i;
    }
}

// ---------------- kernel 2: warp-per-valid-box classify/bucket ----------------
__global__ void k_classify(const float* __restrict__ det) {
    int gw   = (blockIdx.x * blockDim.x + threadIdx.x) >> 5;
    int lane = threadIdx.x & 31;
    if (gw >= g_nvalid) return;

    int vid = g_vidx[gw];
    const float* p = det + (size_t)vid * STRIDE;

    float a  = p[lane];
    float b2 = p[lane + 32];
    float c2 = (lane < 21) ? p[lane + 64] : -1e30f;

    float bv = -1e30f; int bi = 0;
    if (lane >= 5)            { bv = a;  bi = lane - 5;  }
    if (b2 > bv)              { bv = b2; bi = lane + 27; }
    if (lane < 21 && c2 > bv) { bv = c2; bi = lane + 59; }

    #pragma unroll
    for (int off = 16; off; off >>= 1) {
        float ov = __shfl_down_sync(FULLMASK, bv, off);
        int   oi = __shfl_down_sync(FULLMASK, bi, off);
        if (ov > bv || (ov == bv && oi < bi)) { bv = ov; bi = oi; }
    }

    float x = __shfl_sync(FULLMASK, a, 0);
    float y = __shfl_sync(FULLMASK, a, 1);
    float w = __shfl_sync(FULLMASK, a, 2);
    float h = __shfl_sync(FULLMASK, a, 3);
    float o = __shfl_sync(FULLMASK, a, 4);

    if (lane == 0) {
        float conf  = bv;
        float score = __fmul_rn(o, conf);
        float hw = __fmul_rn(w, 0.5f);
        float hh = __fmul_rn(h, 0.5f);
        int shard = blockIdx.x & (NSHARD - 1);
        int local = atomicAdd(&g_cnt4[bi * NSHARD + shard], 1);
        if (local < SHARDCAP) {
            int idx = bi * CAP + shard * SHARDCAP + local;
            g_x1[idx] = __fsub_rn(x, hw);
            g_y1[idx] = __fsub_rn(y, hh);
            g_x2[idx] = __fadd_rn(x, hw);
            g_y2[idx] = __fadd_rn(y, hh);
            g_sc[idx] = score;
            g_cf[idx] = conf;
        }
    }
}

// ---------------- kernel 3: per-class NMS (hybrid bitonic + 1-sync greedy) ----------------
__global__ __launch_bounds__(1024) void k_nms() {
    __shared__ float sk[1024];
    __shared__ int   si[1024];
    __shared__ float sx1[1024], sy1[1024], sx2[1024], sy2[1024];
    __shared__ float skey[1024], sconf[1024];
    __shared__ int   s_next[3];

    int c = blockIdx.x;
    int t = threadIdx.x;
    int base = c * CAP;

    // live count
    int n = 0;
    {
        int v0 = g_cnt4[c * NSHARD + 0]; n += (v0 > SHARDCAP) ? SHARDCAP : v0;
        int v1 = g_cnt4[c * NSHARD + 1]; n += (v1 > SHARDCAP) ? SHARDCAP : v1;
        int v2 = g_cnt4[c * NSHARD + 2]; n += (v2 > SHARDCAP) ? SHARDCAP : v2;
        int v3 = g_cnt4[c * NSHARD + 3]; n += (v3 > SHARDCAP) ? SHARDCAP : v3;
    }
    if (n == 0) return;

    // slot-based load: empty slots hold -inf (from k_init)
    float key = g_sc[base + t];
    int   id  = t;

    // hybrid bitonic sort, M = 1024, (key desc, id asc)
    #pragma unroll
    for (int k = 2; k <= 1024; k <<= 1) {
        #pragma unroll
        for (int j = k >> 1; j > 0; j >>= 1) {
            bool dir  = ((t & k) == 0);
            bool iLow = ((t & j) == 0);
            float pk; int pi;
            if (j >= 32) {
                sk[t] = key; si[t] = id;
                __syncthreads();
                pk = sk[t ^ j]; pi = si[t ^ j];
                __syncthreads();
            } else {
                pk = __shfl_xor_sync(FULLMASK, key, j);
                pi = __shfl_xor_sync(FULLMASK, id,  j);
            }
            if (before(key, id, pk, pi) != (iLow == dir)) { key = pk; id = pi; }
        }
    }

    // gather coords/conf in sorted order; thread t owns sorted position t
    float bx1 = g_x1[base + id], by1 = g_y1[base + id];
    float bx2 = g_x2[base + id], by2 = g_y2[base + id];
    skey[t]  = key;
    sconf[t] = g_cf[base + id];
    sx1[t] = bx1; sy1[t] = by1; sx2[t] = bx2; sy2[t] = by2;
    if (t < 3) s_next[t] = n;
    __syncthreads();

    float a2 = __fmul_rn(__fadd_rn(__fsub_rn(bx2, bx1), 1.0f),
                         __fadd_rn(__fsub_rn(by2, by1), 1.0f));
    bool alive = (t < n);
    int lane = t & 31;

    int cur = 0, p = 0;
    while (cur < n) {
        if (t == 0) {
            int kk = atomicAdd(&g_keep_n, 1);
            if (kk < MAXKEEP) {
                g_keep_score[kk] = skey[cur];
                g_keep_conf [kk] = sconf[cur];
                g_keep_cls  [kk] = c;
            }
            // reset the slot that will be used two iterations from now;
            // its readers all passed the *next* barrier already.
            s_next[(p + 2) % 3] = n;
        }

        float px1 = sx1[cur], py1 = sy1[cur], px2 = sx2[cur], py2 = sy2[cur];
        float pa  = __fmul_rn(__fadd_rn(__fsub_rn(px2, px1), 1.0f),
                              __fadd_rn(__fsub_rn(py2, py1), 1.0f));

        int cand = n;
        if (alive && t > cur) {
            float xx1 = fmaxf(px1, bx1), yy1 = fmaxf(py1, by1);
            float xx2 = fminf(px2, bx2), yy2 = fminf(py2, by2);
            float iw  = fmaxf(__fadd_rn(__fsub_rn(xx2, xx1), 1.0f), 0.0f);
            float ih  = fmaxf(__fadd_rn(__fsub_rn(yy2, yy1), 1.0f), 0.0f);
            float inter = __fmul_rn(iw, ih);
            float den = __fadd_rn(__fsub_rn(__fadd_rn(pa, a2), inter), 1e-16f);
            float iou = __fdiv_rn(inter, den);
            if (iou > NMS_THRES) alive = false;
            else                 cand = t;
        }
        #pragma unroll
        for (int off = 16; off; off >>= 1)
            cand = min(cand, __shfl_xor_sync(FULLMASK, cand, off));
        if (lane == 0 && cand < n) atomicMin(&s_next[p], cand);
        __syncthreads();
        cur = s_next[p];
        p = (p + 1) % 3;
    }
}

// ---------------- kernel 4: score sort (dyn bitonic) + conf re-rank, emit ----------------
__global__ __launch_bounds__(1024) void k_final(float* __restrict__ out, int out_size) {
    __shared__ float sk[2048];
    __shared__ int   si[2048];
    __shared__ float s_conf[MAX_DET];
    __shared__ int   s_cls [MAX_DET];
    __shared__ float s_outc[MAX_DET];
    __shared__ float s_outp[MAX_DET];

    int t = threadIdx.x;
    int K = g_keep_n; if (K > MAXKEEP) K = MAXKEEP;
    int Kc = (K < MAX_DET) ? K : MAX_DET;

    if (t < MAX_DET) { s_outc[t] = 0.0f; s_outp[t] = 0.0f; }

    if (K <= 1024) {
        // single-element hybrid bitonic over dynamic m (pow2, >=32)
        int m = 32; while (m < K) m <<= 1;
        float key = -CUDART_INF_F; int id = t;
        if (t < K) key = g_keep_score[t];

        for (int k = 2; k <= m; k <<= 1) {
            for (int j = k >> 1; j > 0; j >>= 1) {
                if (j >= 32) {
                    if (t < m) { sk[t] = key; si[t] = id; }
                    __syncthreads();
                    float pk = 0.0f; int pi = 0;
                    if (t < m) { pk = sk[t ^ j]; pi = si[t ^ j]; }
                    __syncthreads();
                    if (t < m) {
                        bool dir  = ((t & k) == 0);
                        bool iLow = ((t & j) == 0);
                        if (before(key, id, pk, pi) != (iLow == dir)) { key = pk; id = pi; }
                    }
                } else if (t < m) {     // warps are wholly inside/outside m (m pow2 >= 32)
                    float pk = __shfl_xor_sync(FULLMASK, key, j);
                    int   pi = __shfl_xor_sync(FULLMASK, id,  j);
                    bool dir  = ((t & k) == 0);
                    bool iLow = ((t & j) == 0);
                    if (before(key, id, pk, pi) != (iLow == dir)) { key = pk; id = pi; }
                }
            }
        }
        if (t < Kc) { s_conf[t] = g_keep_conf[id]; s_cls[t] = g_keep_cls[id]; }
    } else {
        // two-element hybrid bitonic over M = 2048 (R2-proven path)
        float k0 = (t        < K) ? g_keep_score[t]        : -CUDART_INF_F;
        float k1 = (t + 1024 < K) ? g_keep_score[t + 1024] : -CUDART_INF_F;
        int   i0 = t, i1 = t + 1024;

        #pragma unroll
        for (int k = 2; k <= 2048; k <<= 1) {
            #pragma unroll
            for (int j = k >> 1; j > 0; j >>= 1) {
                if (j == 1024) {
                    if (!before(k0, i0, k1, i1)) {
                        float tk = k0; k0 = k1; k1 = tk;
                        int   ti = i0; i0 = i1; i1 = ti;
                    }
                } else if (j >= 32) {
                    sk[t] = k0; si[t] = i0;
                    sk[t + 1024] = k1; si[t + 1024] = i1;
                    __syncthreads();
                    float p0 = sk[t ^ j];          int q0 = si[t ^ j];
                    float p1 = sk[(t ^ j) + 1024]; int q1 = si[(t ^ j) + 1024];
                    __syncthreads();
                    bool iLow = ((t & j) == 0);
                    bool d0 = ((t & k) == 0);
                    bool d1 = (((t + 1024) & k) == 0);
                    if (before(k0, i0, p0, q0) != (iLow == d0)) { k0 = p0; i0 = q0; }
                    if (before(k1, i1, p1, q1) != (iLow == d1)) { k1 = p1; i1 = q1; }
                } else {
                    bool iLow = ((t & j) == 0);
                    bool d0 = ((t & k) == 0);
                    bool d1 = (((t + 1024) & k) == 0);
                    float p0 = __shfl_xor_sync(FULLMASK, k0, j);
                    int   q0 = __shfl_xor_sync(FULLMASK, i0, j);
                    float p1 = __shfl_xor_sync(FULLMASK, k1, j);
                    int   q1 = __shfl_xor_sync(FULLMASK, i1, j);
                    if (before(k0, i0, p0, q0) != (iLow == d0)) { k0 = p0; i0 = q0; }
                    if (before(k1, i1, p1, q1) != (iLow == d1)) { k1 = p1; i1 = q1; }
                }
            }
        }
        if (t < Kc) { s_conf[t] = g_keep_conf[i0]; s_cls[t] = g_keep_cls[i0]; }
    }
    __syncthreads();

    // conf re-rank over Kc <= 300 (conf desc, ties -> larger score-rank first)
    if (t < Kc) {
        float mc = s_conf[t];
        int pos = 0;
        for (int j = 0; j < Kc; j++) {
            float oc = s_conf[j];
            if ((oc > mc) || (oc == mc && j > t)) pos++;
        }
        s_outc[pos] = (float)s_cls[t];
        s_outp[pos] = mc;
    }
    __syncthreads();

    if (t < MAX_DET) {
        if (t < out_size)            out[t]           = s_outc[t];
        if (MAX_DET + t < out_size)  out[MAX_DET + t] = s_outp[t];
    }
}

// ---------------- launch ----------------
extern "C" void kernel_launch(void* const* d_in, const int* in_sizes, int n_in,
                              void* d_out, int out_size) {
    const float* det = (const float*)d_in[0];
    float* out = (float*)d_out;

    k_init<<<(N_CLASSES * CAP + 255) / 256, 256>>>();
    k_probe<<<N_BOXES / 256, 256>>>(det);
    k_classify<<<CLS_WARPS / 8, 256>>>(det);
    k_nms<<<N_CLASSES, 1024>>>();
    k_final<<<1, 1024>>>(out, out_size);
}

// round 6
// speedup vs baseline: 1.7375x; 1.0300x over previous
#include <cuda_runtime.h>
#include <cuda_bf16.h>
#include <math_constants.h>
#include <cstdint>

#define N_BOXES   262144
#define STRIDE    85
#define N_CLASSES 80
#define CONF_THRES 0.8f
#define NMS_THRES  0.4f
#define MAX_DET    300
#define NSHARD    4
#define SHARDCAP  256
#define CAP       (NSHARD * SHARDCAP)   // 1024 slots per class
#define MAXKEEP   2048
#define FULLMASK  0xffffffffu
#define CLS_WARPS 57344

// ---------------- device scratch ----------------
__device__ int   g_cnt4[N_CLASSES * NSHARD];
__device__ float g_x1[N_CLASSES * CAP];
__device__ float g_y1[N_CLASSES * CAP];
__device__ float g_x2[N_CLASSES * CAP];
__device__ float g_y2[N_CLASSES * CAP];
__device__ float g_sc[N_CLASSES * CAP];
__device__ float g_cf[N_CLASSES * CAP];

__device__ int   g_nvalid;      // reset in k_nms (NOT in k_probe: same-kernel race)
__device__ int   g_vidx[N_BOXES];

__device__ int   g_keep_n;
__device__ int   g_done;
__device__ float g_keep_score[MAXKEEP];
__device__ float g_keep_conf [MAXKEEP];
__device__ int   g_keep_cls  [MAXKEEP];

__device__ __forceinline__ bool before(float ak, int ai, float bk, int bi) {
    return (ak > bk) || (ak == bk && ai < bi);
}

// ---------------- kernel 1: init + obj probe + compaction (fused) ----------------
// NOTE: g_nvalid is NOT reset here — it is incremented in this kernel, and an
// in-kernel reset races with other blocks' atomicAdds across graph replays.
// It is zero at first call (static init) and reset by k_nms each replay.
__global__ void k_probe(const float* __restrict__ det) {
    int i = blockIdx.x * blockDim.x + threadIdx.x;
    int lane = threadIdx.x & 31;

    // init section (consumers are in LATER kernels -> safe)
    if (i < N_CLASSES * CAP) g_sc[i] = -CUDART_INF_F;
    if (i < N_CLASSES * NSHARD) g_cnt4[i] = 0;
    if (i == 0) { g_keep_n = 0; g_done = 0; }

    // probe section
    float obj = det[(size_t)i * STRIDE + 4];
    bool v = (obj >= CONF_THRES);
    unsigned mask = __ballot_sync(FULLMASK, v);
    int npop = __popc(mask);
    int base = 0;
    if (lane == 0 && npop) base = atomicAdd(&g_nvalid, npop);
    base = __shfl_sync(FULLMASK, base, 0);
    if (v) {
        int off = __popc(mask & ((1u << lane) - 1u));
        g_vidx[base + off] = i;
    }
}

// ---------------- kernel 2: warp-per-valid-box classify/bucket ----------------
__global__ void k_classify(const float* __restrict__ det) {
    int gw   = (blockIdx.x * blockDim.x + threadIdx.x) >> 5;
    int lane = threadIdx.x & 31;
    if (gw >= g_nvalid) return;

    int vid = g_vidx[gw];
    const float* p = det + (size_t)vid * STRIDE;

    float a  = p[lane];
    float b2 = p[lane + 32];
    float c2 = (lane < 21) ? p[lane + 64] : -1e30f;

    float bv = -1e30f; int bi = 0;
    if (lane >= 5)            { bv = a;  bi = lane - 5;  }
    if (b2 > bv)              { bv = b2; bi = lane + 27; }
    if (lane < 21 && c2 > bv) { bv = c2; bi = lane + 59; }

    #pragma unroll
    for (int off = 16; off; off >>= 1) {
        float ov = __shfl_down_sync(FULLMASK, bv, off);
        int   oi = __shfl_down_sync(FULLMASK, bi, off);
        if (ov > bv || (ov == bv && oi < bi)) { bv = ov; bi = oi; }
    }

    float x = __shfl_sync(FULLMASK, a, 0);
    float y = __shfl_sync(FULLMASK, a, 1);
    float w = __shfl_sync(FULLMASK, a, 2);
    float h = __shfl_sync(FULLMASK, a, 3);
    float o = __shfl_sync(FULLMASK, a, 4);

    if (lane == 0) {
        float conf  = bv;
        float score = __fmul_rn(o, conf);
        float hw = __fmul_rn(w, 0.5f);
        float hh = __fmul_rn(h, 0.5f);
        int shard = blockIdx.x & (NSHARD - 1);
        int local = atomicAdd(&g_cnt4[bi * NSHARD + shard], 1);
        if (local < SHARDCAP) {
            int idx = bi * CAP + shard * SHARDCAP + local;
            g_x1[idx] = __fsub_rn(x, hw);
            g_y1[idx] = __fsub_rn(y, hh);
            g_x2[idx] = __fadd_rn(x, hw);
            g_y2[idx] = __fadd_rn(y, hh);
            g_sc[idx] = score;
            g_cf[idx] = conf;
        }
    }
}

// ---------------- kernel 3: per-class NMS + fused final (last block) ----------------
__global__ __launch_bounds__(1024) void k_nms(float* __restrict__ out, int out_size) {
    __shared__ __align__(16) unsigned char s_raw[32768];

    // --- aliased layout ---
    float* SK    = (float*)(s_raw);
    int*   SI    = (int*)  (s_raw + 4096);
    int*   S_KEEP= (int*)  (s_raw);
    int*   S_WMIN= (int*)  (s_raw + 4096);
    int*   S_MISC= (int*)  (s_raw + 4352);
    float* SX1   = (float*)(s_raw + 8192);
    float* SY1   = (float*)(s_raw + 12288);
    float* SX2   = (float*)(s_raw + 16384);
    float* SY2   = (float*)(s_raw + 20480);
    float* SKEY  = (float*)(s_raw + 24576);
    float* SCONF = (float*)(s_raw + 28672);
    float* FK    = (float*)(s_raw);
    int*   FI    = (int*)  (s_raw + 8192);
    float* FCONF = (float*)(s_raw + 16384);
    int*   FCLS  = (int*)  (s_raw + 17664);
    float* FOUTC = (float*)(s_raw + 18944);
    float* FOUTP = (float*)(s_raw + 20224);

    int c = blockIdx.x;
    int t = threadIdx.x;
    int lane = t & 31;
    int wid  = t >> 5;
    int base = c * CAP;

    // cross-replay reset: k_classify (this replay) is done; k_probe of the
    // NEXT replay needs g_nvalid == 0.
    if (c == 0 && t == 0) g_nvalid = 0;

    int n = 0;
    {
        int v0 = g_cnt4[c * NSHARD + 0]; n += (v0 > SHARDCAP) ? SHARDCAP : v0;
        int v1 = g_cnt4[c * NSHARD + 1]; n += (v1 > SHARDCAP) ? SHARDCAP : v1;
        int v2 = g_cnt4[c * NSHARD + 2]; n += (v2 > SHARDCAP) ? SHARDCAP : v2;
        int v3 = g_cnt4[c * NSHARD + 3]; n += (v3 > SHARDCAP) ? SHARDCAP : v3;
    }

    if (n > 0) {
        // ---- hybrid bitonic sort, M = 1024, (key desc, id asc) ----
        float key = g_sc[base + t];    // empty slots hold -inf
        int   id  = t;

        #pragma unroll
        for (int k = 2; k <= 1024; k <<= 1) {
            #pragma unroll
            for (int j = k >> 1; j > 0; j >>= 1) {
                bool dir  = ((t & k) == 0);
                bool iLow = ((t & j) == 0);
                float pk; int pi;
                if (j >= 32) {
                    SK[t] = key; SI[t] = id;
                    __syncthreads();
                    pk = SK[t ^ j]; pi = SI[t ^ j];
                    __syncthreads();
                } else {
                    pk = __shfl_xor_sync(FULLMASK, key, j);
                    pi = __shfl_xor_sync(FULLMASK, id,  j);
                }
                if (before(key, id, pk, pi) != (iLow == dir)) { key = pk; id = pi; }
            }
        }

        // ---- gather coords/conf in sorted order ----
        float bx1 = g_x1[base + id], by1 = g_y1[base + id];
        float bx2 = g_x2[base + id], by2 = g_y2[base + id];
        SKEY[t]  = key;
        SCONF[t] = g_cf[base + id];
        SX1[t] = bx1; SY1[t] = by1; SX2[t] = bx2; SY2[t] = by2;
        __syncthreads();   // retires SK/SI aliases before S_KEEP/S_WMIN use

        float a2 = __fmul_rn(__fadd_rn(__fsub_rn(bx2, bx1), 1.0f),
                             __fadd_rn(__fsub_rn(by2, by1), 1.0f));
        bool alive = (t < n);

        // ---- greedy loop: zero atomics, 1 barrier per pick ----
        int np = 0;           // uniform across block
        int cur = 0, par = 0;
        while (cur < n) {
            if (t == 0) S_KEEP[np] = cur;
            np++;

            float px1 = SX1[cur], py1 = SY1[cur], px2 = SX2[cur], py2 = SY2[cur];
            float pa  = __fmul_rn(__fadd_rn(__fsub_rn(px2, px1), 1.0f),
                                  __fadd_rn(__fsub_rn(py2, py1), 1.0f));

            int cand = n;
            if (alive && t > cur) {
                float xx1 = fmaxf(px1, bx1), yy1 = fmaxf(py1, by1);
                float xx2 = fminf(px2, bx2), yy2 = fminf(py2, by2);
                float iw  = fmaxf(__fadd_rn(__fsub_rn(xx2, xx1), 1.0f), 0.0f);
                float ih  = fmaxf(__fadd_rn(__fsub_rn(yy2, yy1), 1.0f), 0.0f);
                float inter = __fmul_rn(iw, ih);
                float den = __fadd_rn(__fsub_rn(__fadd_rn(pa, a2), inter), 1e-16f);
                float iou = __fdiv_rn(inter, den);
                if (iou > NMS_THRES) alive = false;
                else                 cand = t;
            }
            #pragma unroll
            for (int off = 16; off; off >>= 1)
                cand = min(cand, __shfl_xor_sync(FULLMASK, cand, off));
            if (lane == 0) S_WMIN[par * 32 + wid] = cand;
            __syncthreads();
            int v = S_WMIN[par * 32 + lane];
            #pragma unroll
            for (int off = 16; off; off >>= 1)
                v = min(v, __shfl_xor_sync(FULLMASK, v, off));
            cur = v;
            par ^= 1;
        }

        // ---- flush: one global atomic per class ----
        if (t == 0) S_MISC[0] = atomicAdd(&g_keep_n, np);
        __syncthreads();
        int kbase = S_MISC[0];
        if (t < np) {
            int q  = S_KEEP[t];
            int kk = kbase + t;
            if (kk < MAXKEEP) {
                g_keep_score[kk] = SKEY[q];
                g_keep_conf [kk] = SCONF[q];
                g_keep_cls  [kk] = c;
            }
        }
    }

    // ---- last-block-done handoff ----
    __threadfence();
    __syncthreads();
    if (t == 0) S_MISC[1] = (atomicAdd(&g_done, 1) == N_CLASSES - 1) ? 1 : 0;
    __syncthreads();
    if (!S_MISC[1]) return;
    __threadfence();

    // ================= final phase (last-finishing block) =================
    int K = g_keep_n; if (K > MAXKEEP) K = MAXKEEP;
    int Kc = (K < MAX_DET) ? K : MAX_DET;

    __syncthreads();   // retire nms smem aliases before FK/FI use

    if (t < MAX_DET) { FOUTC[t] = 0.0f; FOUTP[t] = 0.0f; }

    if (K <= 1024) {
        int m = 32; while (m < K) m <<= 1;
        float key = -CUDART_INF_F; int id = t;
        if (t < K) key = g_keep_score[t];

        for (int k = 2; k <= m; k <<= 1) {
            for (int j = k >> 1; j > 0; j >>= 1) {
                if (j >= 32) {
                    if (t < m) { FK[t] = key; FI[t] = id; }
                    __syncthreads();
                    float pk = 0.0f; int pi = 0;
                    if (t < m) { pk = FK[t ^ j]; pi = FI[t ^ j]; }
                    __syncthreads();
                    if (t < m) {
                        bool dir  = ((t & k) == 0);
                        bool iLow = ((t & j) == 0);
                        if (before(key, id, pk, pi) != (iLow == dir)) { key = pk; id = pi; }
                    }
                } else if (t < m) {
                    float pk = __shfl_xor_sync(FULLMASK, key, j);
                    int   pi = __shfl_xor_sync(FULLMASK, id,  j);
                    bool dir  = ((t & k) == 0);
                    bool iLow = ((t & j) == 0);
                    if (before(key, id, pk, pi) != (iLow == dir)) { key = pk; id = pi; }
                }
            }
        }
        if (t < Kc) { FCONF[t] = g_keep_conf[id]; FCLS[t] = g_keep_cls[id]; }
    } else {
        float k0 = (t        < K) ? g_keep_score[t]        : -CUDART_INF_F;
        float k1 = (t + 1024 < K) ? g_keep_score[t + 1024] : -CUDART_INF_F;
        int   i0 = t, i1 = t + 1024;

        #pragma unroll
        for (int k = 2; k <= 2048; k <<= 1) {
            #pragma unroll
            for (int j = k >> 1; j > 0; j >>= 1) {
                if (j == 1024) {
                    if (!before(k0, i0, k1, i1)) {
                        float tk = k0; k0 = k1; k1 = tk;
                        int   ti = i0; i0 = i1; i1 = ti;
                    }
                } else if (j >= 32) {
                    FK[t] = k0; FI[t] = i0;
                    FK[t + 1024] = k1; FI[t + 1024] = i1;
                    __syncthreads();
                    float p0 = FK[t ^ j];          int q0 = FI[t ^ j];
                    float p1 = FK[(t ^ j) + 1024]; int q1 = FI[(t ^ j) + 1024];
                    __syncthreads();
                    bool iLow = ((t & j) == 0);
                    bool d0 = ((t & k) == 0);
                    bool d1 = (((t + 1024) & k) == 0);
                    if (before(k0, i0, p0, q0) != (iLow == d0)) { k0 = p0; i0 = q0; }
                    if (before(k1, i1, p1, q1) != (iLow == d1)) { k1 = p1; i1 = q1; }
                } else {
                    bool iLow = ((t & j) == 0);
                    bool d0 = ((t & k) == 0);
                    bool d1 = (((t + 1024) & k) == 0);
                    float p0 = __shfl_xor_sync(FULLMASK, k0, j);
                    int   q0 = __shfl_xor_sync(FULLMASK, i0, j);
                    float p1 = __shfl_xor_sync(FULLMASK, k1, j);
                    int   q1 = __shfl_xor_sync(FULLMASK, i1, j);
                    if (before(k0, i0, p0, q0) != (iLow == d0)) { k0 = p0; i0 = q0; }
                    if (before(k1, i1, p1, q1) != (iLow == d1)) { k1 = p1; i1 = q1; }
                }
            }
        }
        if (t < Kc) { FCONF[t] = g_keep_conf[i0]; FCLS[t] = g_keep_cls[i0]; }
    }
    __syncthreads();

    // conf re-rank over Kc <= 300 (conf desc, ties -> larger score-rank first)
    if (t < Kc) {
        float mc = FCONF[t];
        int pos = 0;
        for (int j = 0; j < Kc; j++) {
            float oc = FCONF[j];
            if ((oc > mc) || (oc == mc && j > t)) pos++;
        }
        FOUTC[pos] = (float)FCLS[t];
        FOUTP[pos] = mc;
    }
    __syncthreads();

    if (t < MAX_DET) {
        if (t < out_size)            out[t]           = FOUTC[t];
        if (MAX_DET + t < out_size)  out[MAX_DET + t] = FOUTP[t];
    }
}

// ---------------- launch ----------------
extern "C" void kernel_launch(void* const* d_in, const int* in_sizes, int n_in,
                              void* d_out, int out_size) {
    const float* det = (const float*)d_in[0];
    float* out = (float*)d_out;

    k_probe<<<N_BOXES / 256, 256>>>(det);
    k_classify<<<CLS_WARPS / 8, 256>>>(det);
    k_nms<<<N_CLASSES, 1024>>>(out, out_size);
}